// round 6
// baseline (speedup 1.0000x reference)
#include <cuda_runtime.h>
#include <math.h>

#define BATCH 256
#define DI    5120
#define RNK   160
#define NS    16
#define RX    192            // 160 (delta) + 16 (B) + 16 (C)

#define KS1   40             // split-K factor for GEMM1
#define KCH   (DI / KS1)     // 128
#define BT1   16             // batch tile GEMM1
#define WCH   16             // w prefetch chunk GEMM1

#define BT2   8              // batch tile GEMM2
#define DCH2  256            // threads / d-chunk GEMM2
#define RCH   8              // Wdt prefetch chunk GEMM2

#define LOG2E 1.4426950408889634f

// ---- scratch (no dynamic allocation allowed) ----
__device__ float g_part[KS1 * BATCH * RX];   // GEMM1 split-K partials
__device__ float g_xd[BATCH * RX];           // [xd | Bp | C]
__device__ float g_dt[BATCH * DI];           // softplus(delta)
__device__ float g_negA[DI * NS];            // [d][n]: -exp(A_log)*log2e

// ---------------------------------------------------------------- prep
__global__ void k_prep(const float* __restrict__ A_log) {
    int i = blockIdx.x * blockDim.x + threadIdx.x;
    if (i < DI * NS) g_negA[i] = -expf(A_log[i]) * LOG2E;
}

// ---------------------------------------------------------------- GEMM1 core
template <int WSTR>
__device__ __forceinline__ void gemm1_core(const float* __restrict__ w0,
                                           const float* __restrict__ xs,
                                           float* __restrict__ acc) {
    float wbuf[2][WCH];
    const float* wp = w0;
#pragma unroll
    for (int j = 0; j < WCH; j++) wbuf[0][j] = wp[j * WSTR];

    for (int c = 0; c < KCH / WCH; c++) {
        const int cur = c & 1;
        if (c + 1 < KCH / WCH) {
            const float* wn = wp + WCH * WSTR;
#pragma unroll
            for (int j = 0; j < WCH; j++) wbuf[cur ^ 1][j] = wn[j * WSTR];
        }
#pragma unroll
        for (int j = 0; j < WCH; j++) {
            float w = wbuf[cur][j];
            const float4* xv4 = reinterpret_cast<const float4*>(xs + (c * WCH + j) * BT1);
#pragma unroll
            for (int q = 0; q < BT1 / 4; q++) {
                float4 xv = xv4[q];
                acc[4*q+0] += xv.x * w;
                acc[4*q+1] += xv.y * w;
                acc[4*q+2] += xv.z * w;
                acc[4*q+3] += xv.w * w;
            }
        }
        wp += WCH * WSTR;
    }
}

// ---------------------------------------------------------------- GEMM1
__global__ void __launch_bounds__(RX)
k_gemm1(const float* __restrict__ x,
        const float* __restrict__ Wd,
        const float* __restrict__ WB,
        const float* __restrict__ WC) {
    __shared__ float xs[KCH * BT1];         // [kk][bb]  8 KB
    const int r  = threadIdx.x;             // 0..191
    const int b0 = blockIdx.x * BT1;
    const int k0 = blockIdx.y * KCH;

    for (int i = r; i < KCH * BT1; i += RX) {
        int bb = i / KCH, kk = i - bb * KCH;
        xs[kk * BT1 + bb] = x[(b0 + bb) * DI + k0 + kk];
    }

    float acc[BT1];
#pragma unroll
    for (int i = 0; i < BT1; i++) acc[i] = 0.f;

    __syncthreads();

    if (r < 160) {
        gemm1_core<160>(Wd + r + k0 * 160, xs, acc);
    } else {
        const float* wb = (r < 176) ? (WB + (r - 160) + k0 * 16)
                                    : (WC + (r - 176) + k0 * 16);
        gemm1_core<16>(wb, xs, acc);
    }

    float* out = g_part + (blockIdx.y * BATCH + b0) * RX + r;
#pragma unroll
    for (int bb = 0; bb < BT1; bb++) out[bb * RX] = acc[bb];
}

// ---------------------------------------------------------------- reduce
__global__ void k_reduce() {
    int i = blockIdx.x * blockDim.x + threadIdx.x;    // float4 index
    if (i >= BATCH * RX / 4) return;
    const float4* p = reinterpret_cast<const float4*>(g_part) + i;
    float4 s = make_float4(0.f, 0.f, 0.f, 0.f);
#pragma unroll
    for (int ks = 0; ks < KS1; ks++) {
        float4 v = p[ks * (BATCH * RX / 4)];
        s.x += v.x; s.y += v.y; s.z += v.z; s.w += v.w;
    }
    reinterpret_cast<float4*>(g_xd)[i] = s;
}

// ---------------------------------------------------------------- GEMM2 + softplus
// dt[b][d] = softplus( sum_r xd[b][r] * Wdt[r][d] + b_dt[d] )
__global__ void __launch_bounds__(DCH2)
k_gemm2(const float* __restrict__ Wdt,
        const float* __restrict__ b_dt) {
    __shared__ float xds[RNK * BT2];        // [r][bb]  5 KB
    const int tid = threadIdx.x;            // 0..255
    const int d   = blockIdx.x * DCH2 + tid;
    const int b0  = blockIdx.y * BT2;

    for (int i = tid; i < RNK * BT2; i += DCH2) {
        int bb = i / RNK, r = i - bb * RNK;
        xds[r * BT2 + bb] = g_xd[(b0 + bb) * RX + r];
    }
    __syncthreads();

    float acc[BT2];
#pragma unroll
    for (int i = 0; i < BT2; i++) acc[i] = 0.f;

    const float* wp = Wdt + d;
    float wbuf[2][RCH];
#pragma unroll
    for (int j = 0; j < RCH; j++) wbuf[0][j] = wp[j * DI];

    for (int c = 0; c < RNK / RCH; c++) {
        const int cur = c & 1;
        if (c + 1 < RNK / RCH) {
            const float* wn = wp + RCH * DI;
#pragma unroll
            for (int j = 0; j < RCH; j++) wbuf[cur ^ 1][j] = wn[j * DI];
        }
        const int rbase = c * RCH;
#pragma unroll
        for (int j = 0; j < RCH; j++) {
            float w = wbuf[cur][j];
            const float4* xv4 = reinterpret_cast<const float4*>(xds + (rbase + j) * BT2);
            float4 x0 = xv4[0];
            float4 x1 = xv4[1];
            acc[0] += x0.x * w;  acc[1] += x0.y * w;
            acc[2] += x0.z * w;  acc[3] += x0.w * w;
            acc[4] += x1.x * w;  acc[5] += x1.y * w;
            acc[6] += x1.z * w;  acc[7] += x1.w * w;
        }
        wp += RCH * DI;
    }

    float bv = b_dt[d];
#pragma unroll
    for (int bb = 0; bb < BT2; bb++) {
        float z = acc[bb] + bv;
        g_dt[(b0 + bb) * DI + d] = (z > 20.f) ? z : log1pf(expf(z));
    }
}

// ---------------------------------------------------------------- SSM streaming readout
// y[b][d] = sum_n exp2(dt * negA[d,n]) * h[b,d,n] * C[b,n]
//           + x[b,d] * ( dt * dot(B,C) + D[d] )
__global__ void __launch_bounds__(256)
k_ssm(const float* __restrict__ x,
      const float* __restrict__ h,
      const float* __restrict__ Dv,
      float* __restrict__ y) {
    __shared__ float sC[NS];
    __shared__ float sbc;
    const int b = blockIdx.y;
    const int d = blockIdx.x * 256 + threadIdx.x;

    if (threadIdx.x < 2 * NS) {
        float v = g_xd[b * RX + 160 + threadIdx.x];
        if (threadIdx.x >= NS) sC[threadIdx.x - NS] = v;
    }
    __syncthreads();
    if (threadIdx.x == 0) {
        float s = 0.f;
        const float* bp = &g_xd[b * RX + 160];
#pragma unroll
        for (int n = 0; n < NS; n++) s += bp[n] * sC[n];
        sbc = s;
    }

    // issue all independent loads up front (MLP ~ 10)
    float dtv = g_dt[b * DI + d];
    float xv  = x[b * DI + d];
    const float4* hp = reinterpret_cast<const float4*>(h) + (b * DI + d) * (NS / 4);
    const float4* ap = reinterpret_cast<const float4*>(g_negA) + d * (NS / 4);
    float4 hv0 = hp[0], hv1 = hp[1], hv2 = hp[2], hv3 = hp[3];
    float4 na0 = ap[0], na1 = ap[1], na2 = ap[2], na3 = ap[3];
    float Dval = Dv[d];

    __syncthreads();   // sbc ready

    float a2 = 0.f;
    a2 += exp2f(dtv * na0.x) * hv0.x * sC[0];
    a2 += exp2f(dtv * na0.y) * hv0.y * sC[1];
    a2 += exp2f(dtv * na0.z) * hv0.z * sC[2];
    a2 += exp2f(dtv * na0.w) * hv0.w * sC[3];
    a2 += exp2f(dtv * na1.x) * hv1.x * sC[4];
    a2 += exp2f(dtv * na1.y) * hv1.y * sC[5];
    a2 += exp2f(dtv * na1.z) * hv1.z * sC[6];
    a2 += exp2f(dtv * na1.w) * hv1.w * sC[7];
    a2 += exp2f(dtv * na2.x) * hv2.x * sC[8];
    a2 += exp2f(dtv * na2.y) * hv2.y * sC[9];
    a2 += exp2f(dtv * na2.z) * hv2.z * sC[10];
    a2 += exp2f(dtv * na2.w) * hv2.w * sC[11];
    a2 += exp2f(dtv * na3.x) * hv3.x * sC[12];
    a2 += exp2f(dtv * na3.y) * hv3.y * sC[13];
    a2 += exp2f(dtv * na3.z) * hv3.z * sC[14];
    a2 += exp2f(dtv * na3.w) * hv3.w * sC[15];

    y[b * DI + d] = a2 + xv * (dtv * sbc + Dval);
}

// ----------------------------------------------------------------
extern "C" void kernel_launch(void* const* d_in, const int* in_sizes, int n_in,
                              void* d_out, int out_size) {
    const float* x    = (const float*)d_in[0];
    const float* h    = (const float*)d_in[1];
    const float* Wd   = (const float*)d_in[2];
    const float* Wdt  = (const float*)d_in[3];
    const float* bdt  = (const float*)d_in[4];
    const float* Alog = (const float*)d_in[5];
    const float* WB   = (const float*)d_in[6];
    const float* WC   = (const float*)d_in[7];
    const float* D    = (const float*)d_in[8];
    float* y = (float*)d_out;

    k_prep  <<<(DI * NS + 255) / 256, 256>>>(Alog);
    k_gemm1 <<<dim3(BATCH / BT1, KS1), RX>>>(x, Wd, WB, WC);
    k_reduce<<<(BATCH * RX / 4 + 255) / 256, 256>>>();
    k_gemm2 <<<dim3(DI / DCH2, BATCH / BT2), DCH2>>>(Wdt, bdt);
    k_ssm   <<<dim3(DI / 256, BATCH), 256>>>(x, h, D, y);
}

// round 7
// speedup vs baseline: 1.1018x; 1.1018x over previous
#include <cuda_runtime.h>
#include <math.h>

#define BATCH 256
#define DI    5120
#define RNK   160
#define NS    16
#define RX    192            // 160 (delta) + 16 (B) + 16 (C)

#define KS1   40             // split-K factor for GEMM1
#define KCH   (DI / KS1)     // 128
#define BT1   16             // batch tile GEMM1
#define WCH   16             // w prefetch chunk GEMM1

#define BT2   8              // batch tile GEMM2
#define DCH2  256            // threads / d-chunk GEMM2
#define RCH   8              // Wdt prefetch chunk GEMM2

#define LOG2E 1.4426950408889634f

// ---- scratch (no dynamic allocation allowed) ----
__device__ float g_part[KS1 * BATCH * RX];   // GEMM1 split-K partials
__device__ float g_xd[BATCH * RX];           // [xd | Bp | C]
__device__ float g_dt[BATCH * DI];           // softplus(delta)
__device__ float g_negA[DI * NS];            // [d][n]: -exp(A_log)*log2e

// ---------------------------------------------------------------- prep
__global__ void k_prep(const float* __restrict__ A_log) {
    int i = blockIdx.x * blockDim.x + threadIdx.x;
    if (i < DI * NS) g_negA[i] = -expf(A_log[i]) * LOG2E;
}

// ---------------------------------------------------------------- GEMM1 core
// FULLY UNROLLED chunk loop: wbuf indices compile-time -> true register buffers.
template <int WSTR>
__device__ __forceinline__ void gemm1_core(const float* __restrict__ w0,
                                           const float* __restrict__ xs,
                                           float* __restrict__ acc) {
    float wbuf[2][WCH];
    const float* wp = w0;
#pragma unroll
    for (int j = 0; j < WCH; j++) wbuf[0][j] = wp[j * WSTR];

#pragma unroll
    for (int c = 0; c < KCH / WCH; c++) {
        const int cur = c & 1;                 // compile-time now
        if (c + 1 < KCH / WCH) {
            const float* wn = wp + WCH * WSTR;
#pragma unroll
            for (int j = 0; j < WCH; j++) wbuf[cur ^ 1][j] = wn[j * WSTR];
        }
#pragma unroll
        for (int j = 0; j < WCH; j++) {
            float w = wbuf[cur][j];
            const float4* xv4 = reinterpret_cast<const float4*>(xs + (c * WCH + j) * BT1);
#pragma unroll
            for (int q = 0; q < BT1 / 4; q++) {
                float4 xv = xv4[q];
                acc[4*q+0] += xv.x * w;
                acc[4*q+1] += xv.y * w;
                acc[4*q+2] += xv.z * w;
                acc[4*q+3] += xv.w * w;
            }
        }
        wp += WCH * WSTR;
    }
}

// ---------------------------------------------------------------- GEMM1
__global__ void __launch_bounds__(RX)
k_gemm1(const float* __restrict__ x,
        const float* __restrict__ Wd,
        const float* __restrict__ WB,
        const float* __restrict__ WC) {
    __shared__ float xs[KCH * BT1];         // [kk][bb]  8 KB
    const int r  = threadIdx.x;             // 0..191
    const int b0 = blockIdx.x * BT1;
    const int k0 = blockIdx.y * KCH;

    for (int i = r; i < KCH * BT1; i += RX) {
        int bb = i / KCH, kk = i - bb * KCH;
        xs[kk * BT1 + bb] = x[(b0 + bb) * DI + k0 + kk];
    }

    float acc[BT1];
#pragma unroll
    for (int i = 0; i < BT1; i++) acc[i] = 0.f;

    __syncthreads();

    if (r < 160) {
        gemm1_core<160>(Wd + r + k0 * 160, xs, acc);
    } else {
        const float* wb = (r < 176) ? (WB + (r - 160) + k0 * 16)
                                    : (WC + (r - 176) + k0 * 16);
        gemm1_core<16>(wb, xs, acc);
    }

    float* out = g_part + (blockIdx.y * BATCH + b0) * RX + r;
#pragma unroll
    for (int bb = 0; bb < BT1; bb++) out[bb * RX] = acc[bb];
}

// ---------------------------------------------------------------- reduce
__global__ void k_reduce() {
    int i = blockIdx.x * blockDim.x + threadIdx.x;    // float4 index
    if (i >= BATCH * RX / 4) return;
    const float4* p = reinterpret_cast<const float4*>(g_part) + i;
    float4 s = make_float4(0.f, 0.f, 0.f, 0.f);
#pragma unroll
    for (int ks = 0; ks < KS1; ks++) {
        float4 v = p[ks * (BATCH * RX / 4)];
        s.x += v.x; s.y += v.y; s.z += v.z; s.w += v.w;
    }
    reinterpret_cast<float4*>(g_xd)[i] = s;
}

// ---------------------------------------------------------------- GEMM2 + softplus
// dt[b][d] = softplus( sum_r xd[b][r] * Wdt[r][d] + b_dt[d] )
__global__ void __launch_bounds__(DCH2)
k_gemm2(const float* __restrict__ Wdt,
        const float* __restrict__ b_dt) {
    __shared__ float xds[RNK * BT2];        // [r][bb]  5 KB
    const int tid = threadIdx.x;            // 0..255
    const int d   = blockIdx.x * DCH2 + tid;
    const int b0  = blockIdx.y * BT2;

    for (int i = tid; i < RNK * BT2; i += DCH2) {
        int bb = i / RNK, r = i - bb * RNK;
        xds[r * BT2 + bb] = g_xd[(b0 + bb) * RX + r];
    }
    __syncthreads();

    float acc[BT2];
#pragma unroll
    for (int i = 0; i < BT2; i++) acc[i] = 0.f;

    const float* wp = Wdt + d;
    float wbuf[2][RCH];
#pragma unroll
    for (int j = 0; j < RCH; j++) wbuf[0][j] = wp[j * DI];

#pragma unroll
    for (int c = 0; c < RNK / RCH; c++) {
        const int cur = c & 1;                 // compile-time now
        if (c + 1 < RNK / RCH) {
            const float* wn = wp + RCH * DI;
#pragma unroll
            for (int j = 0; j < RCH; j++) wbuf[cur ^ 1][j] = wn[j * DI];
        }
        const int rbase = c * RCH;
#pragma unroll
        for (int j = 0; j < RCH; j++) {
            float w = wbuf[cur][j];
            const float4* xv4 = reinterpret_cast<const float4*>(xds + (rbase + j) * BT2);
            float4 x0 = xv4[0];
            float4 x1 = xv4[1];
            acc[0] += x0.x * w;  acc[1] += x0.y * w;
            acc[2] += x0.z * w;  acc[3] += x0.w * w;
            acc[4] += x1.x * w;  acc[5] += x1.y * w;
            acc[6] += x1.z * w;  acc[7] += x1.w * w;
        }
        wp += RCH * DI;
    }

    float bv = b_dt[d];
#pragma unroll
    for (int bb = 0; bb < BT2; bb++) {
        float z = acc[bb] + bv;
        g_dt[(b0 + bb) * DI + d] = (z > 20.f) ? z : log1pf(expf(z));
    }
}

// ---------------------------------------------------------------- SSM streaming readout
// 4 threads per d (lane q owns n-quartet q): h/negA loads fully coalesced.
// y[b][d] = sum_n exp2(dt*negA[d,n]) * h[b,d,n] * C[b,n] + x*(dt*dot(B,C) + D[d])
#define SSM_DPB 64                           // d's per block (256 threads / 4)
__global__ void __launch_bounds__(256)
k_ssm(const float* __restrict__ x,
      const float* __restrict__ h,
      const float* __restrict__ Dv,
      float* __restrict__ y) {
    __shared__ float sC[NS];
    __shared__ float sbc;
    const int b  = blockIdx.y;
    const int t  = threadIdx.x;
    const int dl = t >> 2;                   // 0..63
    const int q  = t & 3;                    // n-quartet
    const int d  = blockIdx.x * SSM_DPB + dl;

    if (t < 2 * NS) {
        float v = g_xd[b * RX + 160 + t];
        if (t >= NS) sC[t - NS] = v;
    }
    __syncthreads();
    if (t == 0) {
        float s = 0.f;
        const float* bp = &g_xd[b * RX + 160];
#pragma unroll
        for (int n = 0; n < NS; n++) s += bp[n] * sC[n];
        sbc = s;
    }

    // coalesced: lane addresses are consecutive 16B across the warp
    float4 hv = reinterpret_cast<const float4*>(h)[(b * DI + d) * (NS / 4) + q];
    float4 na = reinterpret_cast<const float4*>(g_negA)[d * (NS / 4) + q];
    float dtv = g_dt[b * DI + d];

    float4 Cq = *reinterpret_cast<const float4*>(sC + 4 * q);
    float s = exp2f(dtv * na.x) * hv.x * Cq.x
            + exp2f(dtv * na.y) * hv.y * Cq.y
            + exp2f(dtv * na.z) * hv.z * Cq.z
            + exp2f(dtv * na.w) * hv.w * Cq.w;

    // reduce across the 4 lanes of this d
    s += __shfl_xor_sync(0xFFFFFFFF, s, 1);
    s += __shfl_xor_sync(0xFFFFFFFF, s, 2);

    __syncthreads();                         // sbc ready
    if (q == 0) {
        float xv = x[b * DI + d];
        y[b * DI + d] = s + xv * (dtv * sbc + Dv[d]);
    }
}

// ----------------------------------------------------------------
extern "C" void kernel_launch(void* const* d_in, const int* in_sizes, int n_in,
                              void* d_out, int out_size) {
    const float* x    = (const float*)d_in[0];
    const float* h    = (const float*)d_in[1];
    const float* Wd   = (const float*)d_in[2];
    const float* Wdt  = (const float*)d_in[3];
    const float* bdt  = (const float*)d_in[4];
    const float* Alog = (const float*)d_in[5];
    const float* WB   = (const float*)d_in[6];
    const float* WC   = (const float*)d_in[7];
    const float* D    = (const float*)d_in[8];
    float* y = (float*)d_out;

    k_prep  <<<(DI * NS + 255) / 256, 256>>>(Alog);
    k_gemm1 <<<dim3(BATCH / BT1, KS1), RX>>>(x, Wd, WB, WC);
    k_reduce<<<(BATCH * RX / 4 + 255) / 256, 256>>>();
    k_gemm2 <<<dim3(DI / DCH2, BATCH / BT2), DCH2>>>(Wdt, bdt);
    k_ssm   <<<dim3(DI / SSM_DPB, BATCH), 256>>>(x, h, D, y);
}

// round 8
// speedup vs baseline: 1.2033x; 1.0921x over previous
#include <cuda_runtime.h>
#include <math.h>

#define BATCH 256
#define DI    5120
#define RNK   160
#define NS    16
#define RX    192            // 160 (delta) + 16 (B) + 16 (C)

#define KS1   40             // split-K factor for GEMM1
#define KCH   (DI / KS1)     // 128
#define BT1   16             // batch tile GEMM1
#define WCH   16             // w prefetch chunk GEMM1

#define BT2   8              // batch tile fused kernel
#define DCH2  256            // d's (= threads) per fused block
#define RCH   8              // Wdt prefetch chunk

#define LOG2E 1.4426950408889634f

// ---- scratch (no dynamic allocation allowed) ----
__device__ float g_part[KS1 * BATCH * RX];   // GEMM1 split-K partials
__device__ float g_xd[BATCH * RX];           // [xd | Bp | C]
__device__ float g_negA[DI * NS];            // [d][n]: -exp(A_log)*log2e

// ---------------------------------------------------------------- prep
__global__ void k_prep(const float* __restrict__ A_log) {
    int i = blockIdx.x * blockDim.x + threadIdx.x;
    if (i < DI * NS) g_negA[i] = -expf(A_log[i]) * LOG2E;
}

// ---------------------------------------------------------------- GEMM1 core
template <int WSTR>
__device__ __forceinline__ void gemm1_core(const float* __restrict__ w0,
                                           const float* __restrict__ xs,
                                           float* __restrict__ acc) {
    float wbuf[2][WCH];
    const float* wp = w0;
#pragma unroll
    for (int j = 0; j < WCH; j++) wbuf[0][j] = wp[j * WSTR];

#pragma unroll
    for (int c = 0; c < KCH / WCH; c++) {
        const int cur = c & 1;                 // compile-time
        if (c + 1 < KCH / WCH) {
            const float* wn = wp + WCH * WSTR;
#pragma unroll
            for (int j = 0; j < WCH; j++) wbuf[cur ^ 1][j] = wn[j * WSTR];
        }
#pragma unroll
        for (int j = 0; j < WCH; j++) {
            float w = wbuf[cur][j];
            const float4* xv4 = reinterpret_cast<const float4*>(xs + (c * WCH + j) * BT1);
#pragma unroll
            for (int q = 0; q < BT1 / 4; q++) {
                float4 xv = xv4[q];
                acc[4*q+0] += xv.x * w;
                acc[4*q+1] += xv.y * w;
                acc[4*q+2] += xv.z * w;
                acc[4*q+3] += xv.w * w;
            }
        }
        wp += WCH * WSTR;
    }
}

// ---------------------------------------------------------------- GEMM1
__global__ void __launch_bounds__(RX)
k_gemm1(const float* __restrict__ x,
        const float* __restrict__ Wd,
        const float* __restrict__ WB,
        const float* __restrict__ WC) {
    __shared__ float xs[KCH * BT1];         // [kk][bb]  8 KB
    const int r  = threadIdx.x;             // 0..191
    const int b0 = blockIdx.x * BT1;
    const int k0 = blockIdx.y * KCH;

    for (int i = r; i < KCH * BT1; i += RX) {
        int bb = i / KCH, kk = i - bb * KCH;
        xs[kk * BT1 + bb] = x[(b0 + bb) * DI + k0 + kk];
    }

    float acc[BT1];
#pragma unroll
    for (int i = 0; i < BT1; i++) acc[i] = 0.f;

    __syncthreads();

    if (r < 160) {
        gemm1_core<160>(Wd + r + k0 * 160, xs, acc);
    } else {
        const float* wb = (r < 176) ? (WB + (r - 160) + k0 * 16)
                                    : (WC + (r - 176) + k0 * 16);
        gemm1_core<16>(wb, xs, acc);
    }

    float* out = g_part + (blockIdx.y * BATCH + b0) * RX + r;
#pragma unroll
    for (int bb = 0; bb < BT1; bb++) out[bb * RX] = acc[bb];
}

// ---------------------------------------------------------------- reduce
__global__ void k_reduce() {
    int i = blockIdx.x * blockDim.x + threadIdx.x;    // float4 index
    if (i >= BATCH * RX / 4) return;
    const float4* p = reinterpret_cast<const float4*>(g_part) + i;
    float4 s = make_float4(0.f, 0.f, 0.f, 0.f);
#pragma unroll
    for (int ks = 0; ks < KS1; ks++) {
        float4 v = p[ks * (BATCH * RX / 4)];
        s.x += v.x; s.y += v.y; s.z += v.z; s.w += v.w;
    }
    reinterpret_cast<float4*>(g_xd)[i] = s;
}

// ---------------------------------------------------------------- fused GEMM2 + softplus + SSM
// Phase 1: one d per thread, 8 batches -> dt in smem (never HBM).
// Phase 2: 4 lanes per d (coalesced h/negA), shfl-reduce, store y.
__global__ void __launch_bounds__(DCH2)
k_fused2(const float* __restrict__ x,
         const float* __restrict__ h,
         const float* __restrict__ Wdt,
         const float* __restrict__ b_dt,
         const float* __restrict__ Dv,
         float* __restrict__ y) {
    __shared__ float xds[RNK * BT2];        // [r][bb]   5 KB
    __shared__ float sdt[BT2 * DCH2];       // [bb][d]   8 KB
    __shared__ float sBC[BT2 * 2 * NS];     // per batch: B[16] | C[16]
    __shared__ float sbc[BT2];              // dot(B,C) per batch
    const int tid = threadIdx.x;            // 0..255
    const int d   = blockIdx.x * DCH2 + tid;
    const int b0  = blockIdx.y * BT2;

    for (int i = tid; i < RNK * BT2; i += DCH2) {
        int bb = i / RNK, r = i - bb * RNK;
        xds[r * BT2 + bb] = g_xd[(b0 + bb) * RX + r];
    }
    if (tid < BT2 * 2 * NS) {
        int bb = tid >> 5, j = tid & 31;
        sBC[tid] = g_xd[(b0 + bb) * RX + 160 + j];
    }
    __syncthreads();

    if (tid < BT2) {
        float s = 0.f;
#pragma unroll
        for (int n = 0; n < NS; n++) s += sBC[tid * 32 + n] * sBC[tid * 32 + NS + n];
        sbc[tid] = s;
    }

    // ---- Phase 1: GEMM2 (register double-buffered W, fully unrolled)
    float acc[BT2];
#pragma unroll
    for (int i = 0; i < BT2; i++) acc[i] = 0.f;

    const float* wp = Wdt + d;
    float wbuf[2][RCH];
#pragma unroll
    for (int j = 0; j < RCH; j++) wbuf[0][j] = wp[j * DI];

#pragma unroll
    for (int c = 0; c < RNK / RCH; c++) {
        const int cur = c & 1;                 // compile-time
        if (c + 1 < RNK / RCH) {
            const float* wn = wp + RCH * DI;
#pragma unroll
            for (int j = 0; j < RCH; j++) wbuf[cur ^ 1][j] = wn[j * DI];
        }
        const int rbase = c * RCH;
#pragma unroll
        for (int j = 0; j < RCH; j++) {
            float w = wbuf[cur][j];
            const float4* xv4 = reinterpret_cast<const float4*>(xds + (rbase + j) * BT2);
            float4 x0 = xv4[0];
            float4 x1 = xv4[1];
            acc[0] += x0.x * w;  acc[1] += x0.y * w;
            acc[2] += x0.z * w;  acc[3] += x0.w * w;
            acc[4] += x1.x * w;  acc[5] += x1.y * w;
            acc[6] += x1.z * w;  acc[7] += x1.w * w;
        }
        wp += RCH * DI;
    }

    float bv = b_dt[d];
#pragma unroll
    for (int bb = 0; bb < BT2; bb++) {
        float z = acc[bb] + bv;
        sdt[bb * DCH2 + tid] = (z > 20.f) ? z : log1pf(expf(z));
    }
    __syncthreads();                        // sdt, sbc ready

    // ---- Phase 2: SSM readout, 4 lanes per d
    const int dl = tid >> 2;                // 0..63
    const int q  = tid & 3;                 // n-quartet
    const float4* h4  = reinterpret_cast<const float4*>(h);
    const float4* na4 = reinterpret_cast<const float4*>(g_negA);

#pragma unroll
    for (int p = 0; p < DCH2 / 64; p++) {
        const int dd = p * 64 + dl;
        const int dg = blockIdx.x * DCH2 + dd;
        float4 na = na4[dg * (NS / 4) + q];
        float4 Cq;
        float Dval = Dv[dg];                // uniform across q; cheap (L2/L1 hit)
#pragma unroll
        for (int bb = 0; bb < BT2; bb++) {
            float dtv = sdt[bb * DCH2 + dd];
            float4 hv = h4[((b0 + bb) * DI + dg) * (NS / 4) + q];
            Cq = *reinterpret_cast<const float4*>(sBC + bb * 32 + NS + 4 * q);
            float s = exp2f(dtv * na.x) * hv.x * Cq.x
                    + exp2f(dtv * na.y) * hv.y * Cq.y
                    + exp2f(dtv * na.z) * hv.z * Cq.z
                    + exp2f(dtv * na.w) * hv.w * Cq.w;
            s += __shfl_xor_sync(0xFFFFFFFF, s, 1);
            s += __shfl_xor_sync(0xFFFFFFFF, s, 2);
            if (q == 0) {
                float xv = x[(b0 + bb) * DI + dg];
                y[(b0 + bb) * DI + dg] = s + xv * (dtv * sbc[bb] + Dval);
            }
        }
    }
}

// ----------------------------------------------------------------
extern "C" void kernel_launch(void* const* d_in, const int* in_sizes, int n_in,
                              void* d_out, int out_size) {
    const float* x    = (const float*)d_in[0];
    const float* h    = (const float*)d_in[1];
    const float* Wd   = (const float*)d_in[2];
    const float* Wdt  = (const float*)d_in[3];
    const float* bdt  = (const float*)d_in[4];
    const float* Alog = (const float*)d_in[5];
    const float* WB   = (const float*)d_in[6];
    const float* WC   = (const float*)d_in[7];
    const float* D    = (const float*)d_in[8];
    float* y = (float*)d_out;

    k_prep  <<<(DI * NS + 255) / 256, 256>>>(Alog);
    k_gemm1 <<<dim3(BATCH / BT1, KS1), RX>>>(x, Wd, WB, WC);
    k_reduce<<<(BATCH * RX / 4 + 255) / 256, 256>>>();
    k_fused2<<<dim3(DI / DCH2, BATCH / BT2), DCH2>>>(x, h, Wdt, bdt, D, y);
}

// round 9
// speedup vs baseline: 1.2671x; 1.0531x over previous
#include <cuda_runtime.h>
#include <math.h>

#define BATCH 256
#define DI    5120
#define RNK   160
#define NS    16
#define RX    192            // 160 (delta) + 16 (B) + 16 (C)

#define KS1   40             // split-K factor for GEMM1
#define KCH   (DI / KS1)     // 128
#define BT1   16             // batch tile GEMM1
#define WCH   16             // w prefetch chunk GEMM1

#define BT2   4              // batch tile fused kernel (smaller -> 2x parallelism)
#define DCH2  256            // d's (= threads) per fused block
#define RCH   8              // Wdt prefetch chunk

#define LOG2E 1.4426950408889634f

// ---- scratch (no dynamic allocation allowed) ----
__device__ float g_part[KS1 * BATCH * RX];   // GEMM1 split-K partials
__device__ float g_xd[BATCH * RX];           // [xd | Bp | C]
__device__ float g_negA[DI * NS];            // [d][n]: -exp(A_log)*log2e

// ---------------------------------------------------------------- prep
__global__ void k_prep(const float* __restrict__ A_log) {
    int i = blockIdx.x * blockDim.x + threadIdx.x;
    if (i < DI * NS) g_negA[i] = -expf(A_log[i]) * LOG2E;
}

// ---------------------------------------------------------------- GEMM1 core
template <int WSTR>
__device__ __forceinline__ void gemm1_core(const float* __restrict__ w0,
                                           const float* __restrict__ xs,
                                           float* __restrict__ acc) {
    float wbuf[2][WCH];
    const float* wp = w0;
#pragma unroll
    for (int j = 0; j < WCH; j++) wbuf[0][j] = wp[j * WSTR];

#pragma unroll
    for (int c = 0; c < KCH / WCH; c++) {
        const int cur = c & 1;                 // compile-time
        if (c + 1 < KCH / WCH) {
            const float* wn = wp + WCH * WSTR;
#pragma unroll
            for (int j = 0; j < WCH; j++) wbuf[cur ^ 1][j] = wn[j * WSTR];
        }
#pragma unroll
        for (int j = 0; j < WCH; j++) {
            float w = wbuf[cur][j];
            const float4* xv4 = reinterpret_cast<const float4*>(xs + (c * WCH + j) * BT1);
#pragma unroll
            for (int q = 0; q < BT1 / 4; q++) {
                float4 xv = xv4[q];
                acc[4*q+0] += xv.x * w;
                acc[4*q+1] += xv.y * w;
                acc[4*q+2] += xv.z * w;
                acc[4*q+3] += xv.w * w;
            }
        }
        wp += WCH * WSTR;
    }
}

// ---------------------------------------------------------------- GEMM1
__global__ void __launch_bounds__(RX)
k_gemm1(const float* __restrict__ x,
        const float* __restrict__ Wd,
        const float* __restrict__ WB,
        const float* __restrict__ WC) {
    __shared__ float xs[KCH * BT1];         // [kk][bb]  8 KB
    const int r  = threadIdx.x;             // 0..191
    const int b0 = blockIdx.x * BT1;
    const int k0 = blockIdx.y * KCH;

    for (int i = r; i < KCH * BT1; i += RX) {
        int bb = i / KCH, kk = i - bb * KCH;
        xs[kk * BT1 + bb] = x[(b0 + bb) * DI + k0 + kk];
    }

    float acc[BT1];
#pragma unroll
    for (int i = 0; i < BT1; i++) acc[i] = 0.f;

    __syncthreads();

    if (r < 160) {
        gemm1_core<160>(Wd + r + k0 * 160, xs, acc);
    } else {
        const float* wb = (r < 176) ? (WB + (r - 160) + k0 * 16)
                                    : (WC + (r - 176) + k0 * 16);
        gemm1_core<16>(wb, xs, acc);
    }

    float* out = g_part + (blockIdx.y * BATCH + b0) * RX + r;
#pragma unroll
    for (int bb = 0; bb < BT1; bb++) out[bb * RX] = acc[bb];
}

// ---------------------------------------------------------------- reduce
__global__ void k_reduce() {
    int i = blockIdx.x * blockDim.x + threadIdx.x;    // float4 index
    if (i >= BATCH * RX / 4) return;
    const float4* p = reinterpret_cast<const float4*>(g_part) + i;
    float4 s = make_float4(0.f, 0.f, 0.f, 0.f);
#pragma unroll
    for (int ks = 0; ks < KS1; ks++) {
        float4 v = p[ks * (BATCH * RX / 4)];
        s.x += v.x; s.y += v.y; s.z += v.z; s.w += v.w;
    }
    reinterpret_cast<float4*>(g_xd)[i] = s;
}

// ---------------------------------------------------------------- fused GEMM2 + softplus + SSM
// BT2=4: 1280 blocks -> ~69 warps/SM demanded, ~55 regs -> 32 resident.
// Phase 1: one d per thread, 4 batches -> dt in smem.
// Phase 2: 4 lanes per d; all 4 batches' h loads issued before any exp work.
__global__ void __launch_bounds__(DCH2)
k_fused2(const float* __restrict__ x,
         const float* __restrict__ h,
         const float* __restrict__ Wdt,
         const float* __restrict__ b_dt,
         const float* __restrict__ Dv,
         float* __restrict__ y) {
    __shared__ float xds[RNK * BT2];        // [r][bb]   2.5 KB
    __shared__ float sdt[BT2 * DCH2];       // [bb][d]   4 KB
    __shared__ float sBC[BT2 * 2 * NS];     // per batch: B[16] | C[16]
    __shared__ float sbc[BT2];              // dot(B,C) per batch
    const int tid = threadIdx.x;            // 0..255
    const int d   = blockIdx.x * DCH2 + tid;
    const int b0  = blockIdx.y * BT2;

    for (int i = tid; i < RNK * BT2; i += DCH2) {
        int bb = i / RNK, r = i - bb * RNK;
        xds[r * BT2 + bb] = g_xd[(b0 + bb) * RX + r];
    }
    if (tid < BT2 * 2 * NS) {
        int bb = tid >> 5, j = tid & 31;
        sBC[tid] = g_xd[(b0 + bb) * RX + 160 + j];
    }
    __syncthreads();

    if (tid < BT2) {
        float s = 0.f;
#pragma unroll
        for (int n = 0; n < NS; n++) s += sBC[tid * 32 + n] * sBC[tid * 32 + NS + n];
        sbc[tid] = s;
    }

    // ---- Phase 1: GEMM2 (register double-buffered W, fully unrolled)
    float acc[BT2];
#pragma unroll
    for (int i = 0; i < BT2; i++) acc[i] = 0.f;

    const float* wp = Wdt + d;
    float wbuf[2][RCH];
#pragma unroll
    for (int j = 0; j < RCH; j++) wbuf[0][j] = wp[j * DI];

#pragma unroll
    for (int c = 0; c < RNK / RCH; c++) {
        const int cur = c & 1;                 // compile-time
        if (c + 1 < RNK / RCH) {
            const float* wn = wp + RCH * DI;
#pragma unroll
            for (int j = 0; j < RCH; j++) wbuf[cur ^ 1][j] = wn[j * DI];
        }
        const int rbase = c * RCH;
#pragma unroll
        for (int j = 0; j < RCH; j++) {
            float w = wbuf[cur][j];
            float4 xv = *reinterpret_cast<const float4*>(xds + (rbase + j) * BT2);
            acc[0] += xv.x * w;  acc[1] += xv.y * w;
            acc[2] += xv.z * w;  acc[3] += xv.w * w;
        }
        wp += RCH * DI;
    }

    float bv = b_dt[d];
#pragma unroll
    for (int bb = 0; bb < BT2; bb++) {
        float z = acc[bb] + bv;
        sdt[bb * DCH2 + tid] = (z > 20.f) ? z : log1pf(expf(z));
    }
    __syncthreads();                        // sdt, sbc ready

    // ---- Phase 2: SSM readout, 4 lanes per d, batched loads (MLP>=4)
    const int dl = tid >> 2;                // 0..63
    const int q  = tid & 3;                 // n-quartet
    const float4* h4  = reinterpret_cast<const float4*>(h);
    const float4* na4 = reinterpret_cast<const float4*>(g_negA);

#pragma unroll
    for (int p = 0; p < DCH2 / 64; p++) {
        const int dd = p * 64 + dl;
        const int dg = blockIdx.x * DCH2 + dd;

        // issue all independent loads first
        float4 na = na4[dg * (NS / 4) + q];
        float4 hv[BT2];
#pragma unroll
        for (int bb = 0; bb < BT2; bb++)
            hv[bb] = h4[((b0 + bb) * DI + dg) * (NS / 4) + q];
        float dts[BT2];
#pragma unroll
        for (int bb = 0; bb < BT2; bb++) dts[bb] = sdt[bb * DCH2 + dd];
        float Dval = Dv[dg];

#pragma unroll
        for (int bb = 0; bb < BT2; bb++) {
            float4 Cq = *reinterpret_cast<const float4*>(sBC + bb * 32 + NS + 4 * q);
            float dtv = dts[bb];
            float s = exp2f(dtv * na.x) * hv[bb].x * Cq.x
                    + exp2f(dtv * na.y) * hv[bb].y * Cq.y
                    + exp2f(dtv * na.z) * hv[bb].z * Cq.z
                    + exp2f(dtv * na.w) * hv[bb].w * Cq.w;
            s += __shfl_xor_sync(0xFFFFFFFF, s, 1);
            s += __shfl_xor_sync(0xFFFFFFFF, s, 2);
            if (q == 0) {
                float xv = x[(b0 + bb) * DI + dg];
                y[(b0 + bb) * DI + dg] = s + xv * (dtv * sbc[bb] + Dval);
            }
        }
    }
}

// ----------------------------------------------------------------
extern "C" void kernel_launch(void* const* d_in, const int* in_sizes, int n_in,
                              void* d_out, int out_size) {
    const float* x    = (const float*)d_in[0];
    const float* h    = (const float*)d_in[1];
    const float* Wd   = (const float*)d_in[2];
    const float* Wdt  = (const float*)d_in[3];
    const float* bdt  = (const float*)d_in[4];
    const float* Alog = (const float*)d_in[5];
    const float* WB   = (const float*)d_in[6];
    const float* WC   = (const float*)d_in[7];
    const float* D    = (const float*)d_in[8];
    float* y = (float*)d_out;

    k_prep  <<<(DI * NS + 255) / 256, 256>>>(Alog);
    k_gemm1 <<<dim3(BATCH / BT1, KS1), RX>>>(x, Wd, WB, WC);
    k_reduce<<<(BATCH * RX / 4 + 255) / 256, 256>>>();
    k_fused2<<<dim3(DI / DCH2, BATCH / BT2), DCH2>>>(x, h, Wdt, bdt, D, y);
}